// round 12
// baseline (speedup 1.0000x reference)
#include <cuda_runtime.h>
#include <cuda_bf16.h>
#include <cstdint>

// TextureMartingaleModule: x[8,16,256,256] f32 -> out[8,64,256,256] f32
// R9 -> R12: issue-bound (issue 80.8%, fma+alu ~77%, DRAM only 40%).
//  - packed f32x2 column sums (FADD2/FFMA2; ptxas never emits these from C++)
//  - rsqrt/rcp.approx MUFU paths instead of IEEE sqrt/div sequences
//  - q stored as p*log2(p+eps); ln2 folded into entropy output constant
//  - all (f+eps)*exp(-0.5) scalings fused into single FFMAs
//  - vectorized (LDG.128) halo fill, row-predicated zero padding
// (R11 fix: PTX mnemonic is rsqrt.approx.f32, not rsq.approx.f32)

#define IMG_H 256
#define IMG_W 256
#define TW 64
#define TH 32
#define SROWS (TH + 2)   // 34
#define SSTRIDE 68       // 272 B rows: 16B-aligned for vector LDS

__device__ __forceinline__ float f_rsq(float x) { float r; asm("rsqrt.approx.f32 %0,%1;" : "=f"(r) : "f"(x)); return r; }
__device__ __forceinline__ float f_rcp(float x) { float r; asm("rcp.approx.f32 %0,%1;" : "=f"(r) : "f"(x)); return r; }
__device__ __forceinline__ float f_lg2(float x) { float r; asm("lg2.approx.f32 %0,%1;" : "=f"(r) : "f"(x)); return r; }

__device__ __forceinline__ void add2(uint64_t& d, uint64_t a) {
    asm("add.rn.f32x2 %0,%0,%1;" : "+l"(d) : "l"(a));
}
__device__ __forceinline__ void fma2(uint64_t& d, uint64_t a) {
    asm("fma.rn.f32x2 %0,%1,%1,%0;" : "+l"(d) : "l"(a));
}
__device__ __forceinline__ void unpack2(float& lo, float& hi, uint64_t p) {
    asm("mov.b64 {%0,%1},%2;" : "=f"(lo), "=f"(hi) : "l"(p));
}

__global__ __launch_bounds__(256, 3)
void texture_martingale_kernel(const float* __restrict__ x,
                               float* __restrict__ out)
{
    __shared__ __align__(16) float sp[SROWS][SSTRIDE];
    __shared__ __align__(16) float sq[SROWS][SSTRIDE];

    const int img = blockIdx.z;
    const int x0  = blockIdx.x * TW;
    const int y0  = blockIdx.y * TH;
    const float* __restrict__ base = x + (size_t)img * (IMG_H * IMG_W);

    const int tid = threadIdx.x;
    const float EPSF = 1e-6f;

    // ---- Vectorized halo fill: 34 rows x 16 float4 segments (cols 1..64) ----
    #pragma unroll
    for (int u = tid; u < SROWS * 16; u += 256) {
        int r = u >> 4, s = u & 15;
        int gy = y0 + r - 1;
        int c  = 1 + 4 * s;                  // gx = x0 + 4s (16B-aligned)
        float4 v = make_float4(0.f, 0.f, 0.f, 0.f);
        if ((unsigned)gy < (unsigned)IMG_H)
            v = *reinterpret_cast<const float4*>(base + gy * IMG_W + x0 + 4 * s);
        sp[r][c + 0] = v.x;  sq[r][c + 0] = v.x * f_lg2(v.x + EPSF);
        sp[r][c + 1] = v.y;  sq[r][c + 1] = v.y * f_lg2(v.y + EPSF);
        sp[r][c + 2] = v.z;  sq[r][c + 2] = v.z * f_lg2(v.z + EPSF);
        sp[r][c + 3] = v.w;  sq[r][c + 3] = v.w * f_lg2(v.w + EPSF);
    }
    // ---- Edge columns c=0 (gx=x0-1) and c=65 (gx=x0+64) ----
    if (tid < SROWS * 2) {
        int r = tid >> 1, side = tid & 1;
        int gy = y0 + r - 1;
        int c  = side ? 65 : 0;
        int gx = x0 + (side ? 64 : -1);
        float p = 0.f;
        if ((unsigned)gy < (unsigned)IMG_H && (unsigned)gx < (unsigned)IMG_W)
            p = base[gy * IMG_W + gx];
        sp[r][c] = p;
        sq[r][c] = p * f_lg2(p + EPSF);
    }
    __syncthreads();

    // ---- Each thread: 4 x-consecutive outputs in 2 consecutive rows ----
    const int tx = tid & 15;
    const int ty = tid >> 4;
    const int cx = tx * 4;           // taps span cols cx..cx+5
    const int ry = ty * 2;           // halo rows ry..ry+3

    // Packed accumulators: [window][pair] pairs = cols (0,1)(2,3)(4,5)
    uint64_t c1P[2][3] = {}, c2P[2][3] = {}, cqP[2][3] = {};

    #pragma unroll
    for (int r = 0; r < 4; r++) {
        uint32_t pa = (uint32_t)__cvta_generic_to_shared(&sp[ry + r][cx]);
        uint32_t qa = (uint32_t)__cvta_generic_to_shared(&sq[ry + r][cx]);
        uint64_t p0, p1, p2, q0, q1, q2;
        asm("ld.shared.v2.b64 {%0,%1},[%2];" : "=l"(p0), "=l"(p1) : "r"(pa));
        asm("ld.shared.b64 %0,[%1+16];"      : "=l"(p2)           : "r"(pa));
        asm("ld.shared.v2.b64 {%0,%1},[%2];" : "=l"(q0), "=l"(q1) : "r"(qa));
        asm("ld.shared.b64 %0,[%1+16];"      : "=l"(q2)           : "r"(qa));

        if (r < 3) {   // window 0: rows 0..2
            add2(c1P[0][0], p0); add2(c1P[0][1], p1); add2(c1P[0][2], p2);
            fma2(c2P[0][0], p0); fma2(c2P[0][1], p1); fma2(c2P[0][2], p2);
            add2(cqP[0][0], q0); add2(cqP[0][1], q1); add2(cqP[0][2], q2);
        }
        if (r > 0) {   // window 1: rows 1..3
            add2(c1P[1][0], p0); add2(c1P[1][1], p1); add2(c1P[1][2], p2);
            fma2(c2P[1][0], p0); fma2(c2P[1][1], p1); fma2(c2P[1][2], p2);
            add2(cqP[1][0], q0); add2(cqP[1][1], q1); add2(cqP[1][2], q2);
        }
    }

    const float INV9   = 1.0f / 9.0f;
    const float ENH    = 0.60653065971263342f;          // exp(-0.5)
    const float EPSENH = 1e-6f * 0.60653065971263342f;  // eps*exp(-0.5)
    const float C_E    = 0.60653065971263342f / 9.0f;   // ENH/9
    const float C_N    = -0.69314718055994531f * 0.60653065971263342f / 9.0f; // -ln2*ENH/9
    const size_t plane = (size_t)IMG_H * IMG_W;

    #pragma unroll
    for (int w = 0; w < 2; w++) {
        float c1s[6], c2s[6], cqs[6];
        #pragma unroll
        for (int k = 0; k < 3; k++) {
            unpack2(c1s[2 * k], c1s[2 * k + 1], c1P[w][k]);
            unpack2(c2s[2 * k], c2s[2 * k + 1], c2P[w][k]);
            unpack2(cqs[2 * k], cqs[2 * k + 1], cqP[w][k]);
        }

        // Re-load 3 tap rows for homogeneity (hot smem)
        float pr[3][6];
        #pragma unroll
        for (int r = 0; r < 3; r++) {
            const float4 a4 = *reinterpret_cast<const float4*>(&sp[ry + w + r][cx]);
            const float2 a2 = *reinterpret_cast<const float2*>(&sp[ry + w + r][cx + 4]);
            pr[r][0] = a4.x; pr[r][1] = a4.y; pr[r][2] = a4.z;
            pr[r][3] = a4.w; pr[r][4] = a2.x; pr[r][5] = a2.y;
        }

        float oc[4], oe[4], on[4], oh[4];
        #pragma unroll
        for (int j = 0; j < 4; j++) {
            float s1 = c1s[j] + c1s[j + 1] + c1s[j + 2];
            float s2 = c2s[j] + c2s[j + 1] + c2s[j + 2];
            float sl = cqs[j] + cqs[j + 1] + cqs[j + 2];

            float m  = s1 * INV9;
            float v  = fmaxf(fmaf(-s1, m, s2), 0.0f);   // sum (p-m)^2
            float u  = fmaf(v, 0.125f, 1e-38f);          // v/8, NaN-guarded
            float sd = u * f_rsq(u) + EPSF;              // sqrt(v/8)+eps
            oc[j] = fmaf(v * C_E, f_rcp(sd * sd), EPSENH);
            oe[j] = fmaf(s2, C_E, EPSENH);
            on[j] = fmaf(sl, C_N, EPSENH);

            float sa = 0.0f;
            #pragma unroll
            for (int r = 0; r < 3; r++) {
                #pragma unroll
                for (int c = 0; c < 3; c++)
                    sa += fabsf(pr[r][j + c] - m);
            }
            oh[j] = fmaf(f_rcp(fmaf(sa, INV9, 1.0f)), ENH, EPSENH);
        }

        float* ob = out + (size_t)img * 4 * plane
                        + (size_t)(y0 + ry + w) * IMG_W + x0 + cx;
        *reinterpret_cast<float4*>(ob + 0 * plane) = make_float4(oc[0], oc[1], oc[2], oc[3]);
        *reinterpret_cast<float4*>(ob + 1 * plane) = make_float4(oe[0], oe[1], oe[2], oe[3]);
        *reinterpret_cast<float4*>(ob + 2 * plane) = make_float4(on[0], on[1], on[2], on[3]);
        *reinterpret_cast<float4*>(ob + 3 * plane) = make_float4(oh[0], oh[1], oh[2], oh[3]);
    }
}

extern "C" void kernel_launch(void* const* d_in, const int* in_sizes, int n_in,
                              void* d_out, int out_size)
{
    const float* x = (const float*)d_in[0];
    float* out = (float*)d_out;

    dim3 grid(IMG_W / TW, IMG_H / TH, 8 * 16);  // (4, 8, 128)
    dim3 block(256);
    texture_martingale_kernel<<<grid, block>>>(x, out);
}

// round 14
// speedup vs baseline: 1.0710x; 1.0710x over previous
#include <cuda_runtime.h>
#include <cuda_bf16.h>
#include <cstdint>

// TextureMartingaleModule: x[8,16,256,256] f32 -> out[8,64,256,256] f32
// R12 post-mortem: packed-f32x2 asm serialized accumulator chains + register-pair
// bloat -> latency-bound (issue 47%). R13 = R9's compiler-scheduled scalar body
// + R12's proven instruction deletions:
//  - MUFU rsqrt/rcp/lg2 approx instead of IEEE sqrt/div sequences
//  - q stored as p*log2(p+eps); ln2 + (f+eps)*exp(-0.5) folded into FFMA consts
//  - vectorized (LDG.128) halo fill, row-predicated zero padding

#define IMG_H 256
#define IMG_W 256
#define TW 64
#define TH 32
#define SROWS (TH + 2)   // 34
#define SSTRIDE 68       // 272 B rows: 16B-aligned for vector LDS

__device__ __forceinline__ float f_rsq(float x) { float r; asm("rsqrt.approx.f32 %0,%1;" : "=f"(r) : "f"(x)); return r; }
__device__ __forceinline__ float f_rcp(float x) { float r; asm("rcp.approx.f32 %0,%1;" : "=f"(r) : "f"(x)); return r; }
__device__ __forceinline__ float f_lg2(float x) { float r; asm("lg2.approx.f32 %0,%1;" : "=f"(r) : "f"(x)); return r; }

__global__ __launch_bounds__(256, 3)
void texture_martingale_kernel(const float* __restrict__ x,
                               float* __restrict__ out)
{
    __shared__ __align__(16) float sp[SROWS][SSTRIDE];
    __shared__ __align__(16) float sq[SROWS][SSTRIDE];

    const int img = blockIdx.z;
    const int x0  = blockIdx.x * TW;
    const int y0  = blockIdx.y * TH;
    const float* __restrict__ base = x + (size_t)img * (IMG_H * IMG_W);

    const int tid = threadIdx.x;
    const float EPSF = 1e-6f;

    // ---- Vectorized halo fill: 34 rows x 16 float4 segments (cols 1..64) ----
    #pragma unroll
    for (int u = tid; u < SROWS * 16; u += 256) {
        int r = u >> 4, s = u & 15;
        int gy = y0 + r - 1;
        int c  = 1 + 4 * s;                  // gx = x0 + 4s (16B-aligned load)
        float4 v = make_float4(0.f, 0.f, 0.f, 0.f);
        if ((unsigned)gy < (unsigned)IMG_H)
            v = *reinterpret_cast<const float4*>(base + gy * IMG_W + x0 + 4 * s);
        sp[r][c + 0] = v.x;  sq[r][c + 0] = v.x * f_lg2(v.x + EPSF);
        sp[r][c + 1] = v.y;  sq[r][c + 1] = v.y * f_lg2(v.y + EPSF);
        sp[r][c + 2] = v.z;  sq[r][c + 2] = v.z * f_lg2(v.z + EPSF);
        sp[r][c + 3] = v.w;  sq[r][c + 3] = v.w * f_lg2(v.w + EPSF);
    }
    // ---- Edge columns c=0 (gx=x0-1) and c=65 (gx=x0+64) ----
    if (tid < SROWS * 2) {
        int r = tid >> 1, side = tid & 1;
        int gy = y0 + r - 1;
        int c  = side ? 65 : 0;
        int gx = x0 + (side ? 64 : -1);
        float p = 0.f;
        if ((unsigned)gy < (unsigned)IMG_H && (unsigned)gx < (unsigned)IMG_W)
            p = base[gy * IMG_W + gx];
        sp[r][c] = p;
        sq[r][c] = p * f_lg2(p + EPSF);
    }
    __syncthreads();

    // ---- Each thread: 4 x-consecutive outputs in 2 consecutive rows ----
    const int tx = tid & 15;
    const int ty = tid >> 4;
    const int cx = tx * 4;           // taps span cols cx..cx+5
    const int ry = ty * 2;           // halo rows ry..ry+3

    float pv[4][6];
    float c1w[2][6], c2w[2][6], cqw[2][6];
    #pragma unroll
    for (int c = 0; c < 6; c++) {
        c1w[0][c] = c1w[1][c] = 0.f;
        c2w[0][c] = c2w[1][c] = 0.f;
        cqw[0][c] = cqw[1][c] = 0.f;
    }

    #pragma unroll
    for (int r = 0; r < 4; r++) {
        const float4 a4 = *reinterpret_cast<const float4*>(&sp[ry + r][cx]);
        const float2 a2 = *reinterpret_cast<const float2*>(&sp[ry + r][cx + 4]);
        const float4 b4 = *reinterpret_cast<const float4*>(&sq[ry + r][cx]);
        const float2 b2 = *reinterpret_cast<const float2*>(&sq[ry + r][cx + 4]);
        float pr[6] = {a4.x, a4.y, a4.z, a4.w, a2.x, a2.y};
        float qr[6] = {b4.x, b4.y, b4.z, b4.w, b2.x, b2.y};

        #pragma unroll
        for (int c = 0; c < 6; c++) {
            pv[r][c] = pr[c];
            float s = pr[c] * pr[c];
            if (r < 3) {                       // window 0: rows 0..2
                c1w[0][c] += pr[c];
                c2w[0][c] += s;
                cqw[0][c] += qr[c];
            }
            if (r > 0) {                       // window 1: rows 1..3
                c1w[1][c] += pr[c];
                c2w[1][c] += s;
                cqw[1][c] += qr[c];
            }
        }
    }

    const float INV9   = 1.0f / 9.0f;
    const float ENH    = 0.60653065971263342f;          // exp(-0.5)
    const float EPSENH = 1e-6f * 0.60653065971263342f;  // eps*exp(-0.5)
    const float C_E    = 0.60653065971263342f / 9.0f;   // ENH/9
    const float C_N    = -0.69314718055994531f * 0.60653065971263342f / 9.0f; // -ln2*ENH/9
    const size_t plane = (size_t)IMG_H * IMG_W;

    #pragma unroll
    for (int w = 0; w < 2; w++) {
        float oc[4], oe[4], on[4], oh[4];

        #pragma unroll
        for (int j = 0; j < 4; j++) {
            float s1 = c1w[w][j] + c1w[w][j + 1] + c1w[w][j + 2];
            float s2 = c2w[w][j] + c2w[w][j + 1] + c2w[w][j + 2];
            float sl = cqw[w][j] + cqw[w][j + 1] + cqw[w][j + 2];

            float m  = s1 * INV9;
            float v  = fmaxf(fmaf(-s1, m, s2), 0.0f);   // sum (p-m)^2
            float u  = fmaf(v, 0.125f, 1e-38f);          // v/8, NaN-guarded
            float sd = u * f_rsq(u) + EPSF;              // sqrt(v/8)+eps
            oc[j] = fmaf(v * C_E, f_rcp(sd * sd), EPSENH);
            oe[j] = fmaf(s2, C_E, EPSENH);
            on[j] = fmaf(sl, C_N, EPSENH);

            float sa = 0.0f;
            #pragma unroll
            for (int r = 0; r < 3; r++) {
                #pragma unroll
                for (int c = 0; c < 3; c++)
                    sa += fabsf(pv[w + r][j + c] - m);
            }
            oh[j] = fmaf(f_rcp(fmaf(sa, INV9, 1.0f)), ENH, EPSENH);
        }

        float* ob = out + (size_t)img * 4 * plane
                        + (size_t)(y0 + ry + w) * IMG_W + x0 + cx;
        *reinterpret_cast<float4*>(ob + 0 * plane) = make_float4(oc[0], oc[1], oc[2], oc[3]);
        *reinterpret_cast<float4*>(ob + 1 * plane) = make_float4(oe[0], oe[1], oe[2], oe[3]);
        *reinterpret_cast<float4*>(ob + 2 * plane) = make_float4(on[0], on[1], on[2], on[3]);
        *reinterpret_cast<float4*>(ob + 3 * plane) = make_float4(oh[0], oh[1], oh[2], oh[3]);
    }
}

extern "C" void kernel_launch(void* const* d_in, const int* in_sizes, int n_in,
                              void* d_out, int out_size)
{
    const float* x = (const float*)d_in[0];
    float* out = (float*)d_out;

    dim3 grid(IMG_W / TW, IMG_H / TH, 8 * 16);  // (4, 8, 128)
    dim3 block(256);
    texture_martingale_kernel<<<grid, block>>>(x, out);
}

// round 17
// speedup vs baseline: 1.1429x; 1.0671x over previous
#include <cuda_runtime.h>
#include <cuda_bf16.h>

// TextureMartingaleModule: x[8,16,256,256] f32 -> out[8,64,256,256] f32
// R14 post-mortem: vectorized halo fill (shared by R12/R13) cost ~7us vs R9's
// scalar fill -- the fill is the kernel's MLP/latency-hiding phase, not an
// instruction-count problem. R15 = exact R9 kernel (34.2us, issue 80.8%)
// + pure-deletion constant folding in the output math:
//   v  = fmaf(-s1, m, s2)
//   oe = fmaf(s2, ENH/9, eps*ENH)          (energy: 3 ops -> 1)
//   on = fmaf(sl, -ENH/9, eps*ENH)         (entropy: 3 ops -> 1)
//   oc = fmaf(div, ENH/9, eps*ENH)         (contrast scaling folded)
//   oh = fmaf(hom, ENH, eps*ENH)           (homogeneity scaling folded)

#define IMG_H 256
#define IMG_W 256
#define TW 64           // tile width (outputs)
#define TH 32           // tile height (outputs)
#define SROWS (TH + 2)  // 34
#define SCOLS (TW + 2)  // 66
#define SSTRIDE 68      // 272 B rows: 16B-aligned for float4 LDS

__global__ __launch_bounds__(256, 3)
void texture_martingale_kernel(const float* __restrict__ x,
                               float* __restrict__ out)
{
    __shared__ __align__(16) float sp[SROWS][SSTRIDE];
    __shared__ __align__(16) float sq[SROWS][SSTRIDE];

    const int img = blockIdx.z;                  // b*C + c  (0..127)
    const int x0  = blockIdx.x * TW;
    const int y0  = blockIdx.y * TH;
    const float* __restrict__ base = x + (size_t)img * (IMG_H * IMG_W);

    const int tid = threadIdx.x;

    // ---- Scalar halo fill (R9-proven: 9 independent LDGs/thread = high MLP) ----
    #pragma unroll
    for (int i = tid; i < SROWS * SCOLS; i += 256) {
        int r = i / SCOLS;
        int c = i - r * SCOLS;
        int gy = y0 + r - 1;
        int gx = x0 + c - 1;
        float p = 0.0f;
        if ((unsigned)gy < (unsigned)IMG_H && (unsigned)gx < (unsigned)IMG_W)
            p = __ldg(base + gy * IMG_W + gx);
        sp[r][c] = p;
        sq[r][c] = p * __logf(p + 1e-6f);
    }
    __syncthreads();

    // ---- Each thread: 4 x-consecutive outputs in 2 consecutive rows ----
    const int tx = tid & 15;          // 0..15 -> x quad
    const int ty = tid >> 4;          // 0..15 -> row pair
    const int cx = tx * 4;            // smem col base (taps span cx..cx+5)
    const int ry = ty * 2;            // smem halo row base (rows ry..ry+3)

    float pv[4][6];
    float c1w[2][6], c2w[2][6], cqw[2][6];
    #pragma unroll
    for (int c = 0; c < 6; c++) {
        c1w[0][c] = c1w[1][c] = 0.f;
        c2w[0][c] = c2w[1][c] = 0.f;
        cqw[0][c] = cqw[1][c] = 0.f;
    }

    #pragma unroll
    for (int r = 0; r < 4; r++) {
        const float4 a4 = *reinterpret_cast<const float4*>(&sp[ry + r][cx]);
        const float2 a2 = *reinterpret_cast<const float2*>(&sp[ry + r][cx + 4]);
        const float4 b4 = *reinterpret_cast<const float4*>(&sq[ry + r][cx]);
        const float2 b2 = *reinterpret_cast<const float2*>(&sq[ry + r][cx + 4]);
        float pr[6] = {a4.x, a4.y, a4.z, a4.w, a2.x, a2.y};
        float qr[6] = {b4.x, b4.y, b4.z, b4.w, b2.x, b2.y};

        #pragma unroll
        for (int c = 0; c < 6; c++) {
            pv[r][c] = pr[c];
            float s = pr[c] * pr[c];
            if (r < 3) {                       // window 0: rows 0..2
                c1w[0][c] += pr[c];
                c2w[0][c] += s;
                cqw[0][c] += qr[c];
            }
            if (r > 0) {                       // window 1: rows 1..3
                c1w[1][c] += pr[c];
                c2w[1][c] += s;
                cqw[1][c] += qr[c];
            }
        }
    }

    const float INV9   = 1.0f / 9.0f;
    const float ENH    = 0.60653065971263342f;          // exp(-0.5)
    const float EPSENH = 1e-6f * 0.60653065971263342f;  // eps*exp(-0.5)
    const float C_E    = 0.60653065971263342f / 9.0f;   // ENH/9
    const float C_N    = -0.60653065971263342f / 9.0f;  // -ENH/9 (q uses ln)
    const float EPS    = 1e-6f;
    const size_t plane = (size_t)IMG_H * IMG_W;

    #pragma unroll
    for (int w = 0; w < 2; w++) {
        float oc[4], oe[4], on[4], oh[4];

        #pragma unroll
        for (int j = 0; j < 4; j++) {
            float s1 = c1w[w][j] + c1w[w][j + 1] + c1w[w][j + 2];
            float s2 = c2w[w][j] + c2w[w][j + 1] + c2w[w][j + 2];
            float sl = cqw[w][j] + cqw[w][j + 1] + cqw[w][j + 2];

            float m  = s1 * INV9;
            float v  = fmaxf(fmaf(-s1, m, s2), 0.0f);   // sum (p-m)^2
            float sd = sqrtf(v * 0.125f) + EPS;         // unbiased std + eps
            oc[j] = fmaf(__fdividef(v, sd * sd), C_E, EPSENH);
            oe[j] = fmaf(s2, C_E, EPSENH);
            on[j] = fmaf(sl, C_N, EPSENH);

            float sa = 0.0f;
            #pragma unroll
            for (int r = 0; r < 3; r++) {
                #pragma unroll
                for (int c = 0; c < 3; c++)
                    sa += fabsf(pv[w + r][j + c] - m);
            }
            oh[j] = fmaf(__fdividef(1.0f, fmaf(sa, INV9, 1.0f)), ENH, EPSENH);
        }

        float* ob = out + (size_t)img * 4 * plane
                        + (size_t)(y0 + ry + w) * IMG_W + x0 + cx;
        *reinterpret_cast<float4*>(ob + 0 * plane) = make_float4(oc[0], oc[1], oc[2], oc[3]);
        *reinterpret_cast<float4*>(ob + 1 * plane) = make_float4(oe[0], oe[1], oe[2], oe[3]);
        *reinterpret_cast<float4*>(ob + 2 * plane) = make_float4(on[0], on[1], on[2], on[3]);
        *reinterpret_cast<float4*>(ob + 3 * plane) = make_float4(oh[0], oh[1], oh[2], oh[3]);
    }
}

extern "C" void kernel_launch(void* const* d_in, const int* in_sizes, int n_in,
                              void* d_out, int out_size)
{
    const float* x = (const float*)d_in[0];
    float* out = (float*)d_out;

    dim3 grid(IMG_W / TW, IMG_H / TH, 8 * 16);  // (4, 8, 128)
    dim3 block(256);
    texture_martingale_kernel<<<grid, block>>>(x, out);
}